// round 5
// baseline (speedup 1.0000x reference)
#include <cuda_runtime.h>
#include <cuda_bf16.h>

#define BB 16
#define NN 8192
#define SS 1024
#define KK 32
#define FULLMASK 0xFFFFFFFFu
typedef unsigned long long ull;

// ---------------- scratch (no allocs allowed) ----------------
__device__ float  g_newxyz[BB * SS * 3];   // FPS-selected centers
__device__ float  g_gmax[BB * SS * 3];     // max over K of diff, per coord
__device__ float  g_gsum[BB * SS * 3];     // sum over K of diff, per coord
__device__ double g_acc[2];                // sum(diff), sum(diff^2) for global std
__device__ float  g_lc[BB * 6 * SS];       // pooled features

// ---------------- f32x2 helpers (Blackwell packed fp32) ----------------
__device__ __forceinline__ ull pk2(float lo, float hi) {
    ull r;
    asm("mov.b64 %0, {%1, %2};" : "=l"(r) : "f"(lo), "f"(hi));
    return r;
}
__device__ __forceinline__ void upk2(float& lo, float& hi, ull v) {
    asm("mov.b64 {%0, %1}, %2;" : "=f"(lo), "=f"(hi) : "l"(v));
}
__device__ __forceinline__ ull add2(ull a, ull b) {
    ull r;
    asm("add.rn.f32x2 %0, %1, %2;" : "=l"(r) : "l"(a), "l"(b));
    return r;
}
__device__ __forceinline__ ull mul2(ull a, ull b) {
    ull r;
    asm("mul.rn.f32x2 %0, %1, %2;" : "=l"(r) : "l"(a), "l"(b));
    return r;
}

// ---------------- smem addressing + relaxed ld/st + mapa ----------------
__device__ __forceinline__ unsigned saddr(const void* p) {
    unsigned a;
    asm("{ .reg .u64 t; cvta.to.shared.u64 t, %1; cvt.u32.u64 %0, t; }"
        : "=r"(a) : "l"(p));
    return a;
}
__device__ __forceinline__ void st_cta64(unsigned a, ull v) {
    asm volatile("st.relaxed.cta.shared.u64 [%0], %1;" :: "r"(a), "l"(v));
}
__device__ __forceinline__ ull ld_cta64(unsigned a) {
    ull v;
    asm volatile("ld.relaxed.cta.shared.u64 %0, [%1];" : "=l"(v) : "r"(a));
    return v;
}
__device__ __forceinline__ void st_cta32(unsigned a, unsigned v) {
    asm volatile("st.relaxed.cta.shared.u32 [%0], %1;" :: "r"(a), "r"(v));
}
__device__ __forceinline__ unsigned ld_cta32(unsigned a) {
    unsigned v;
    asm volatile("ld.relaxed.cta.shared.u32 %0, [%1];" : "=r"(v) : "r"(a));
    return v;
}
__device__ __forceinline__ ull ld_clu64(unsigned a) {   // own smem, peer-written
    ull v;
    asm volatile("ld.relaxed.cluster.shared.u64 %0, [%1];" : "=l"(v) : "r"(a));
    return v;
}
__device__ __forceinline__ void st_remote64(unsigned a, ull v) {
    asm volatile("st.relaxed.cluster.shared::cluster.u64 [%0], %1;"
                 :: "r"(a), "l"(v));
}
__device__ __forceinline__ unsigned mapa_rank(unsigned a, unsigned r) {
    unsigned x;
    asm("mapa.shared::cluster.u32 %0, %1, %2;" : "=r"(x) : "r"(a), "r"(r));
    return x;
}

// =====================================================================
// K1: FPS on a 4-CTA cluster per batch (64 blocks x 512 threads).
// Each CTA owns 2048 points (registers). Exact reference math:
//   d = ((dx*dx + dy*dy) + dz*dz), dx = px + (-cx)  [f32x2 packed, rn]
//   distance = min(distance, d); argmax, lowest-index tie-break.
// NO barriers in the step loop: all exchanges (warp->block, CTA->CTA via
// DSMEM) use step-tagged slots + relaxed-scope spin loads. Skew between
// participants is bounded to +-1 step by the data dependency, and slots
// are double-buffered, so tags can never be missed.
// =====================================================================
__global__ void __launch_bounds__(512) __cluster_dims__(4, 1, 1)
fps_kernel(const float* __restrict__ xyz)
{
    const int b = blockIdx.x >> 2;
    const int t = threadIdx.x;
    const int lane = t & 31, warp = t >> 5;
    unsigned rank;
    asm("mov.u32 %0, %%cluster_ctarank;" : "=r"(rank));
    const float* X = xyz + (size_t)b * NN * 3;
    const int pbase = (int)rank * 2048;

    // 4 slots of 512 points; pairs (0,1) and (2,3) packed in f32x2
    ull px2[2], py2[2], pz2[2];
    float dist[4];
#pragma unroll
    for (int i = 0; i < 2; i++) {
        int p0 = pbase + t + ((2 * i) << 9);
        int p1 = pbase + t + ((2 * i + 1) << 9);
        px2[i] = pk2(X[p0 * 3 + 0], X[p1 * 3 + 0]);
        py2[i] = pk2(X[p0 * 3 + 1], X[p1 * 3 + 1]);
        pz2[i] = pk2(X[p0 * 3 + 2], X[p1 * 3 + 2]);
        dist[2 * i] = 1e10f;
        dist[2 * i + 1] = 1e10f;
    }

    __shared__ ull      s_warp[2][16];   // per-warp partials, step-tagged
    __shared__ ull      s_peer[4][2];    // mailboxes by source rank, step-tagged
    __shared__ unsigned s_final[2];      // winner idx, step-tagged

    if (t < 16) { s_warp[0][t] = ~0ull; s_warp[1][t] = ~0ull; }
    if (t < 8)  ((ull*)s_peer)[t] = ~0ull;
    if (t < 2)  s_final[t] = 0xFFFFFFFFu;
    if (t == 0 && blockIdx.x == 0) { g_acc[0] = 0.0; g_acc[1] = 0.0; }
    __syncthreads();
    // all CTAs' mailbox init must complete before any peer store
    asm volatile("barrier.cluster.arrive.aligned;" ::: "memory");
    asm volatile("barrier.cluster.wait.aligned;" ::: "memory");

    const unsigned a_warp  = saddr(&s_warp[0][0]);
    const unsigned a_peer  = saddr(&s_peer[0][0]);
    const unsigned a_final = saddr(&s_final[0]);

    // precompute remote mailbox addresses (lane r sends to CTA r)
    unsigned ra0 = 0, ra1 = 0;
    if (warp == 0 && lane < 4 && lane != (int)rank) {
        ra0 = mapa_rank(a_peer + (rank * 2 + 0) * 8, (unsigned)lane);
        ra1 = mapa_rank(a_peer + (rank * 2 + 1) * 8, (unsigned)lane);
    }

    float cx = X[0], cy = X[1], cz = X[2];   // sample 0 = point 0
    if (rank == 0 && t == 0) {
        float* o = g_newxyz + (size_t)(b * SS) * 3;
        o[0] = cx; o[1] = cy; o[2] = cz;
    }

    for (int s = 0; s < SS - 1; s++) {
        const unsigned tag = (unsigned)(s & 0x7FF);
        const ull ncx2 = pk2(-cx, -cx);
        const ull ncy2 = pk2(-cy, -cy);
        const ull ncz2 = pk2(-cz, -cz);

        float bestv = -1.0f;
#pragma unroll
        for (int i = 0; i < 2; i++) {
            ull dx2 = add2(px2[i], ncx2);
            ull dy2 = add2(py2[i], ncy2);
            ull dz2 = add2(pz2[i], ncz2);
            ull d2 = add2(add2(mul2(dx2, dx2), mul2(dy2, dy2)), mul2(dz2, dz2));
            float d0, d1;
            upk2(d0, d1, d2);
            float n0 = fminf(dist[2 * i], d0);
            float n1 = fminf(dist[2 * i + 1], d1);
            dist[2 * i] = n0;
            dist[2 * i + 1] = n1;
            bestv = fmaxf(bestv, fmaxf(n0, n1));
        }

        // warp argmax via REDUX (dists >= 0 -> float order == u32 bit order)
        unsigned wm = __reduce_max_sync(FULLMASK, __float_as_uint(bestv));
        float wmf = __uint_as_float(wm);
        unsigned cand = 0xFFFFFFFFu;
#pragma unroll
        for (int sl = 3; sl >= 0; sl--)
            cand = (dist[sl] == wmf) ? (unsigned)(pbase + t + (sl << 9)) : cand;
        cand = __reduce_min_sync(FULLMASK, cand);

        if (lane == 0)
            st_cta64(a_warp + ((s & 1) * 16 + warp) * 8,
                     ((ull)wm << 32) | ((ull)tag << 13) | cand);

        if (warp == 0) {
            // gather 16 warp partials (tag-spin)
            ull v = 0;
            if (lane < 16) {
                unsigned aw = a_warp + ((s & 1) * 16 + lane) * 8;
                do { v = ld_cta64(aw); } while (((unsigned)(v >> 13) & 0x7FFu) != tag);
            }
            unsigned val = (lane < 16) ? (unsigned)(v >> 32) : 0u;
            unsigned idx = (lane < 16) ? (unsigned)(v & 0x1FFFull) : 0xFFFFFFFFu;
            unsigned gm = __reduce_max_sync(FULLMASK, val);
            unsigned gi = __reduce_min_sync(FULLMASK,
                                            (val == gm) ? idx : 0xFFFFFFFFu);
            // cluster exchange: lane r<4 handles CTA r
            ull pv = ((ull)gm << 32) | ((ull)tag << 13) | gi;
            if (lane < 4 && lane != (int)rank)
                st_remote64((s & 1) ? ra1 : ra0, pv);
            ull w = 0;
            if (lane < 4) {
                if (lane == (int)rank) w = pv;
                else {
                    unsigned ap = a_peer + (lane * 2 + (s & 1)) * 8;
                    do { w = ld_clu64(ap); } while (((unsigned)(w >> 13) & 0x7FFu) != tag);
                }
            }
            unsigned v2 = (lane < 4) ? (unsigned)(w >> 32) : 0u;
            unsigned i2 = (lane < 4) ? (unsigned)(w & 0x1FFFull) : 0xFFFFFFFFu;
            unsigned gm2 = __reduce_max_sync(FULLMASK, v2);
            unsigned gi2 = __reduce_min_sync(FULLMASK,
                                             (v2 == gm2) ? i2 : 0xFFFFFFFFu);
            if (lane == 0)
                st_cta32(a_final + (s & 1) * 4, (tag << 16) | gi2);
        }

        // all threads: spin for the winner
        unsigned f;
        unsigned af = a_final + (s & 1) * 4;
        do { f = ld_cta32(af); } while ((f >> 16) != tag);
        int widx = (int)(f & 0x1FFFu);

        cx = X[widx * 3 + 0];
        cy = X[widx * 3 + 1];
        cz = X[widx * 3 + 2];
        if (rank == 0 && t == 0) {
            float* o = g_newxyz + (size_t)(b * SS + s + 1) * 3;
            o[0] = cx; o[1] = cy; o[2] = cz;
        }
    }
}

// =====================================================================
// K2: kNN (K=32) + group stats. Warp per query, buffered bitonic top-32.
// key = (orderable(d) << 13) | idx -> ascending u64 order == (d, idx)
// lexicographic order; selected SET == lax.top_k result. Fast path: one
// float compare (d <= kd) per candidate; keys built only in hit chunks.
// `<=` over-admits exact boundary ties; merges keep the 32 smallest keys,
// so the final set is exact.
// =====================================================================
__device__ __forceinline__ ull u64min(ull a, ull b) { return a < b ? a : b; }
__device__ __forceinline__ ull u64max(ull a, ull b) { return a < b ? b : a; }
__device__ __forceinline__ ull makekey(float d, int idx) {
    unsigned ub = __float_as_uint(d);
    ub ^= ((unsigned)((int)ub >> 31)) | 0x80000000u;
    return ((ull)ub << 13) | (unsigned)idx;
}
__device__ __forceinline__ float kth2kd(ull kth) {  // inverse orderable
    unsigned ub = (unsigned)(kth >> 13);
    unsigned db = (ub >> 31) ? (ub ^ 0x80000000u) : ~ub;
    return __uint_as_float(db);
}
__device__ __forceinline__ ull sort32(ull key, int lane)
{
#pragma unroll
    for (int k = 2; k <= 32; k <<= 1) {
#pragma unroll
        for (int j = k >> 1; j > 0; j >>= 1) {
            ull other = __shfl_xor_sync(FULLMASK, key, j);
            bool up = ((lane & k) == 0);
            bool takeMin = (((lane & j) == 0) == up);
            key = takeMin ? u64min(key, other) : u64max(key, other);
        }
    }
    return key;
}
__device__ __forceinline__ ull merge32(ull key, ull buf, int lane)
{
    buf = sort32(buf, lane);
    ull rev = __shfl_sync(FULLMASK, buf, 31 - lane);
    key = u64min(key, rev);
#pragma unroll
    for (int j = 16; j > 0; j >>= 1) {
        ull other = __shfl_xor_sync(FULLMASK, key, j);
        bool takeMin = ((lane & j) == 0);
        key = takeMin ? u64min(key, other) : u64max(key, other);
    }
    return key;
}
// push all candidates flagged in m (uniform) into buffer by rank; merge on fill
__device__ __forceinline__ void push_chunk(ull ck, unsigned m, int lane,
                                           ull& key, ull& kth, float& kd,
                                           ull& buf, int& bcnt)
{
    int cnt = __popc(m);
    int r = lane - bcnt;
    bool take = (r >= 0) && (r < cnt);
    unsigned pos = __fns(m, 0, take ? (r + 1) : 1);
    ull got = __shfl_sync(FULLMASK, ck, pos & 31);
    if (take) buf = got;
    bcnt += cnt;
    if (bcnt >= 32) {
        key = merge32(key, buf, lane);
        kth = __shfl_sync(FULLMASK, key, 31);
        kd = kth2kd(kth);
        int left = bcnt - 32;
        buf = ~0ull;
        if (left) {   // re-push overflow candidates (extras are harmless)
            int start = cnt - left;
            bool tk2 = lane < left;
            unsigned pos2 = __fns(m, 0, tk2 ? (start + lane + 1) : 1);
            ull got2 = __shfl_sync(FULLMASK, ck, pos2 & 31);
            if (tk2) buf = got2;
        }
        bcnt = left;
    }
}

__global__ void __launch_bounds__(1024) knn_kernel(const float* __restrict__ xyz)
{
    extern __shared__ float4 spts[];    // [NN] : x, y, z, |p|^2  (128KB)
    __shared__ double s_p1[32], s_p2[32];

    const int b  = blockIdx.x >> 3;     // 8 query-chunks (128 queries) per batch
    const int qc = blockIdx.x & 7;
    const float* X = xyz + (size_t)b * NN * 3;

    for (int p = threadIdx.x; p < NN; p += 1024) {
        float x = X[p * 3], y = X[p * 3 + 1], z = X[p * 3 + 2];
        float sq = __fadd_rn(__fadd_rn(__fmul_rn(x, x), __fmul_rn(y, y)),
                             __fmul_rn(z, z));
        spts[p] = make_float4(x, y, z, sq);
    }
    __syncthreads();

    const int warp = threadIdx.x >> 5;
    const int lane = threadIdx.x & 31;
    const ull m2two = pk2(-2.0f, -2.0f);

    double acc1 = 0.0, acc2 = 0.0;      // meaningful on lane 0 only

    for (int qi = 0; qi < 4; qi++) {
        const int s = qc * 128 + warp * 4 + qi;
        const float* cen = g_newxyz + (size_t)(b * SS + s) * 3;
        const float cx = cen[0], cy = cen[1], cz = cen[2];
        const float csq = __fadd_rn(__fadd_rn(__fmul_rn(cx, cx), __fmul_rn(cy, cy)),
                                    __fmul_rn(cz, cz));
        const ull cX2 = pk2(cx, cx), cY2 = pk2(cy, cy), cZ2 = pk2(cz, cz);
        const ull csq2 = pk2(csq, csq);

        // init list from candidates 0..63 (sort first 32, merge next 32)
        ull key;
        {
            float4 pt = spts[lane];
            float dot = __fadd_rn(__fadd_rn(__fmul_rn(pt.x, cx), __fmul_rn(pt.y, cy)),
                                  __fmul_rn(pt.z, cz));
            float d = __fadd_rn(__fadd_rn(__fmul_rn(-2.0f, dot), csq), pt.w);
            key = sort32(makekey(d, lane), lane);
            float4 p2 = spts[32 + lane];
            float dot2 = __fadd_rn(__fadd_rn(__fmul_rn(p2.x, cx), __fmul_rn(p2.y, cy)),
                                   __fmul_rn(p2.z, cz));
            float dB = __fadd_rn(__fadd_rn(__fmul_rn(-2.0f, dot2), csq), p2.w);
            key = merge32(key, makekey(dB, 32 + lane), lane);
        }
        ull kth = __shfl_sync(FULLMASK, key, 31);
        float kd = kth2kd(kth);
        ull buf = ~0ull;
        int bcnt = 0;

        for (int base = 64; base < NN; base += 64) {
            const int p0 = base + lane;
            const int p1 = base + 32 + lane;
            float4 a = spts[p0];
            float4 c = spts[p1];
            ull X2 = pk2(a.x, c.x), Y2 = pk2(a.y, c.y);
            ull Z2 = pk2(a.z, c.z), W2 = pk2(a.w, c.w);
            ull dot2 = add2(add2(mul2(X2, cX2), mul2(Y2, cY2)), mul2(Z2, cZ2));
            ull d2 = add2(add2(mul2(m2two, dot2), csq2), W2);
            float d0, d1;
            upk2(d0, d1, d2);
            unsigned h0 = __ballot_sync(FULLMASK, d0 <= kd);
            unsigned h1 = __ballot_sync(FULLMASK, d1 <= kd);
            if (h0 | h1) {
                ull k0 = makekey(d0, p0);
                ull k1 = makekey(d1, p1);
                if (h0) push_chunk(k0, h0, lane, key, kth, kd, buf, bcnt);
                if (h1) {
                    h1 = __ballot_sync(FULLMASK, k1 < kth);
                    if (h1) push_chunk(k1, h1, lane, key, kth, kd, buf, bcnt);
                }
            }
        }
        if (bcnt > 0) key = merge32(key, buf, lane);   // empty slots hold MAX

        // ----- group stats over the kept 32 neighbors -----
        int ki = (int)(key & 0x1FFFull);
        float4 q = spts[ki];
        float dx = __fsub_rn(q.x, cx);
        float dy = __fsub_rn(q.y, cy);
        float dz = __fsub_rn(q.z, cz);
        float sdx = dx, sdy = dy, sdz = dz;
        float mdx = dx, mdy = dy, mdz = dz;
        float s1 = dx + dy + dz;
        float s2 = dx * dx + dy * dy + dz * dz;
#pragma unroll
        for (int o = 16; o; o >>= 1) {
            sdx += __shfl_down_sync(FULLMASK, sdx, o);
            sdy += __shfl_down_sync(FULLMASK, sdy, o);
            sdz += __shfl_down_sync(FULLMASK, sdz, o);
            mdx = fmaxf(mdx, __shfl_down_sync(FULLMASK, mdx, o));
            mdy = fmaxf(mdy, __shfl_down_sync(FULLMASK, mdy, o));
            mdz = fmaxf(mdz, __shfl_down_sync(FULLMASK, mdz, o));
            s1 += __shfl_down_sync(FULLMASK, s1, o);
            s2 += __shfl_down_sync(FULLMASK, s2, o);
        }
        if (lane == 0) {
            int ix = (b * SS + s) * 3;
            g_gsum[ix] = sdx; g_gsum[ix + 1] = sdy; g_gsum[ix + 2] = sdz;
            g_gmax[ix] = mdx; g_gmax[ix + 1] = mdy; g_gmax[ix + 2] = mdz;
            acc1 += (double)s1;
            acc2 += (double)s2;
        }
    }

    // one atomicAdd pair per block
    if (lane == 0) { s_p1[warp] = acc1; s_p2[warp] = acc2; }
    __syncthreads();
    if (threadIdx.x == 0) {
        double a = 0.0, c = 0.0;
        for (int w = 0; w < 32; w++) { a += s_p1[w]; c += s_p2[w]; }
        atomicAdd(&g_acc[0], a);
        atomicAdd(&g_acc[1], c);
    }
}

// =====================================================================
// K3: std, lc, BN1+relu, safe_cdist, BN2+relu. Single block.
// =====================================================================
__global__ void __launch_bounds__(1024) finalize_kernel(
    const float* __restrict__ bn1g, const float* __restrict__ bn1b,
    const float* __restrict__ bn2g, const float* __restrict__ bn2b,
    float* __restrict__ out)
{
    const int t = threadIdx.x;
    const int lane = t & 31, warp = t >> 5;

    __shared__ float s_red[32];
    __shared__ float s_se;
    __shared__ float s_mean[6], s_var[6];
    __shared__ float s_tf[BB * 36];
    __shared__ float s_m2[36], s_v2[36];

    if (t == 0) {
        double M = (double)BB * SS * KK * 3;
        double var = (g_acc[1] - g_acc[0] * g_acc[0] / M) / (M - 1.0); // ddof=1
        s_se = (float)sqrt(var) + 1e-5f;
    }
    __syncthreads();
    const float se = s_se;

    for (int idx = t; idx < BB * SS; idx += 1024) {
        int b = idx >> 10, s = idx & (SS - 1);
        const float* gm = g_gmax + idx * 3;
        const float* gs = g_gsum + idx * 3;
        const float* cn = g_newxyz + idx * 3;
#pragma unroll
        for (int c = 0; c < 3; c++) {
            float mx = __fdiv_rn(gm[c], se);
            float mn = __fdiv_rn(__fdiv_rn(gs[c], 32.0f), se);
            g_lc[(b * 6 + c) * SS + s] = __fadd_rn(mx, mn);
        }
#pragma unroll
        for (int c = 0; c < 3; c++) {
            float v = cn[c];
            g_lc[(b * 6 + 3 + c) * SS + s] = v + v;
        }
    }
    __syncthreads();

    for (int c = 0; c < 6; c++) {
        float part = 0.0f;
        for (int i = t; i < BB * SS; i += 1024) {
            int b = i >> 10, s = i & 1023;
            part += g_lc[(b * 6 + c) * SS + s];
        }
#pragma unroll
        for (int o = 16; o; o >>= 1) part += __shfl_down_sync(FULLMASK, part, o);
        if (lane == 0) s_red[warp] = part;
        __syncthreads();
        if (t == 0) {
            float tot = 0.0f;
            for (int w = 0; w < 32; w++) tot += s_red[w];
            s_mean[c] = tot / (float)(BB * SS);
        }
        __syncthreads();
        float m = s_mean[c];
        part = 0.0f;
        for (int i = t; i < BB * SS; i += 1024) {
            int b = i >> 10, s = i & 1023;
            float d = g_lc[(b * 6 + c) * SS + s] - m;
            part += d * d;
        }
#pragma unroll
        for (int o = 16; o; o >>= 1) part += __shfl_down_sync(FULLMASK, part, o);
        if (lane == 0) s_red[warp] = part;
        __syncthreads();
        if (t == 0) {
            float tot = 0.0f;
            for (int w = 0; w < 32; w++) tot += s_red[w];
            s_var[c] = tot / (float)(BB * SS);   // biased, as in reference
        }
        __syncthreads();
    }
    for (int c = 0; c < 6; c++) {
        float m = s_mean[c], v = s_var[c];
        float g = bn1g[c], bt = bn1b[c];
        float den = sqrtf(v + 1e-5f);
        for (int i = t; i < BB * SS; i += 1024) {
            int b = i >> 10, s = i & 1023;
            int ix = (b * 6 + c) * SS + s;
            float y = (g_lc[ix] - m) / den * g + bt;
            g_lc[ix] = fmaxf(y, 0.0f);
        }
    }
    __syncthreads();

    if (t < BB * 6) {
        int b = t / 6, c = t % 6;
        s_tf[b * 36 + c * 6 + c] = 0.0f;
    }
    for (int task = warp; task < BB * 15; task += 32) {
        int b = task / 15, pr = task % 15;
        int i = 0, j = 0, p = pr;
        for (i = 0; i < 5; i++) {
            int row = 5 - i;
            if (p < row) { j = i + 1 + p; break; }
            p -= row;
        }
        const float* A  = g_lc + (b * 6 + i) * SS;
        const float* Bp = g_lc + (b * 6 + j) * SS;
        float part = 0.0f;
        for (int s = lane; s < SS; s += 32) {
            float d = A[s] - Bp[s];
            part += d * d;
        }
#pragma unroll
        for (int o = 16; o; o >>= 1) part += __shfl_down_sync(FULLMASK, part, o);
        if (lane == 0) {
            float v = part > 0.0f ? sqrtf(part) : 0.0f;
            s_tf[b * 36 + i * 6 + j] = v;
            s_tf[b * 36 + j * 6 + i] = v;
        }
    }
    __syncthreads();

    if (t < 36) {
        float m = 0.0f;
        for (int b = 0; b < BB; b++) m += s_tf[b * 36 + t];
        m /= (float)BB;
        float v = 0.0f;
        for (int b = 0; b < BB; b++) {
            float d = s_tf[b * 36 + t] - m;
            v += d * d;
        }
        v /= (float)BB;
        s_m2[t] = m; s_v2[t] = v;
    }
    __syncthreads();
    if (t < BB * 36) {
        int b = t / 36, f = t % 36;
        float x = s_tf[b * 36 + f];
        float y = (x - s_m2[f]) / sqrtf(s_v2[f] + 1e-5f) * bn2g[f] + bn2b[f];
        out[t] = fmaxf(y, 0.0f);
    }
}

// =====================================================================
extern "C" void kernel_launch(void* const* d_in, const int* in_sizes, int n_in,
                              void* d_out, int out_size)
{
    const float* xyz  = (const float*)d_in[0];
    const float* bn1g = (const float*)d_in[1];
    const float* bn1b = (const float*)d_in[2];
    const float* bn2g = (const float*)d_in[3];
    const float* bn2b = (const float*)d_in[4];
    float* out = (float*)d_out;

    // idempotent host-side attribute set (capture-safe)
    cudaFuncSetAttribute(knn_kernel, cudaFuncAttributeMaxDynamicSharedMemorySize,
                         NN * (int)sizeof(float4));

    fps_kernel<<<BB * 4, 512>>>(xyz);
    knn_kernel<<<BB * 8, 1024, NN * sizeof(float4)>>>(xyz);
    finalize_kernel<<<1, 1024>>>(bn1g, bn1b, bn2g, bn2b, out);
}

// round 6
// speedup vs baseline: 1.4963x; 1.4963x over previous
#include <cuda_runtime.h>
#include <cuda_bf16.h>

#define BB 16
#define NN 8192
#define SS 1024
#define KK 32
#define FULLMASK 0xFFFFFFFFu
typedef unsigned long long ull;

// ---------------- scratch (no allocs allowed) ----------------
__device__ float  g_newxyz[BB * SS * 3];   // FPS-selected centers
__device__ float  g_gmax[BB * SS * 3];     // max over K of diff, per coord
__device__ float  g_gsum[BB * SS * 3];     // sum over K of diff, per coord
__device__ double g_acc[2];                // sum(diff), sum(diff^2) for global std
__device__ float  g_lc[BB * 6 * SS];       // pooled features

// ---------------- f32x2 helpers (Blackwell packed fp32) ----------------
__device__ __forceinline__ ull pk2(float lo, float hi) {
    ull r;
    asm("mov.b64 %0, {%1, %2};" : "=l"(r) : "f"(lo), "f"(hi));
    return r;
}
__device__ __forceinline__ void upk2(float& lo, float& hi, ull v) {
    asm("mov.b64 {%0, %1}, %2;" : "=f"(lo), "=f"(hi) : "l"(v));
}
__device__ __forceinline__ ull add2(ull a, ull b) {
    ull r;
    asm("add.rn.f32x2 %0, %1, %2;" : "=l"(r) : "l"(a), "l"(b));
    return r;
}
__device__ __forceinline__ ull mul2(ull a, ull b) {
    ull r;
    asm("mul.rn.f32x2 %0, %1, %2;" : "=l"(r) : "l"(a), "l"(b));
    return r;
}

// =====================================================================
// K1: FPS. 16 blocks x 1024 threads, 8 pts/thread in registers, packed
// f32x2 math (bitwise identical to scalar rn ops):
//   d = ((dx*dx + dy*dy) + dz*dz), dx = px + (-cx)
//   distance = min(distance, d); argmax, lowest-index tie-break.
// REDUX warp reduces, ONE barrier/step (double-buffered partials, every
// warp redundantly cross-reduces, centroid via L1-resident LDG).
// =====================================================================
__global__ void __launch_bounds__(1024) fps_kernel(const float* __restrict__ xyz)
{
    const int b = blockIdx.x;
    const int t = threadIdx.x;
    const int lane = t & 31, warp = t >> 5;
    const float* X = xyz + (size_t)b * NN * 3;

    // slot s (0..7) -> point t + 1024*s ; pairs (2i, 2i+1) packed
    ull px2[4], py2[4], pz2[4];
    float dist[8];
#pragma unroll
    for (int i = 0; i < 4; i++) {
        int p0 = t + 1024 * (2 * i);
        int p1 = t + 1024 * (2 * i + 1);
        px2[i] = pk2(X[p0 * 3 + 0], X[p1 * 3 + 0]);
        py2[i] = pk2(X[p0 * 3 + 1], X[p1 * 3 + 1]);
        pz2[i] = pk2(X[p0 * 3 + 2], X[p1 * 3 + 2]);
        dist[2 * i] = 1e10f;
        dist[2 * i + 1] = 1e10f;
    }

    __shared__ unsigned s_val[2][32];
    __shared__ int      s_idx[2][32];

    if (t == 0 && b == 0) { g_acc[0] = 0.0; g_acc[1] = 0.0; }  // reset per replay
    // sample 0 = point index 0 (deterministic start, as in reference)
    float cx = X[0], cy = X[1], cz = X[2];
    if (t == 0) {
        float* o = g_newxyz + (size_t)(b * SS) * 3;
        o[0] = cx; o[1] = cy; o[2] = cz;
    }

    for (int s = 0; s < SS - 1; s++) {
        const ull ncx2 = pk2(-cx, -cx);
        const ull ncy2 = pk2(-cy, -cy);
        const ull ncz2 = pk2(-cz, -cz);

        float bestv = -1.0f;
#pragma unroll
        for (int i = 0; i < 4; i++) {
            ull dx2 = add2(px2[i], ncx2);
            ull dy2 = add2(py2[i], ncy2);
            ull dz2 = add2(pz2[i], ncz2);
            ull d2 = add2(add2(mul2(dx2, dx2), mul2(dy2, dy2)), mul2(dz2, dz2));
            float d0, d1;
            upk2(d0, d1, d2);
            float n0 = fminf(dist[2 * i], d0);
            float n1 = fminf(dist[2 * i + 1], d1);
            dist[2 * i] = n0;
            dist[2 * i + 1] = n1;
            bestv = fmaxf(bestv, fmaxf(n0, n1));
        }

        // warp argmax via REDUX (dists >= 0 -> float order == u32 bit order)
        unsigned wm = __reduce_max_sync(FULLMASK, __float_as_uint(bestv));
        float wmf = __uint_as_float(wm);
        unsigned cand = 0x7FFFFFFFu;
#pragma unroll
        for (int sl = 7; sl >= 0; sl--)
            cand = (dist[sl] == wmf) ? (unsigned)(t + (sl << 10)) : cand;
        cand = __reduce_min_sync(FULLMASK, cand);

        if (lane == 0) { s_val[s & 1][warp] = wm; s_idx[s & 1][warp] = (int)cand; }
        __syncthreads();

        // every warp redundantly reduces the 32 per-warp partials
        unsigned v = s_val[s & 1][lane];
        int      ci = s_idx[s & 1][lane];
        unsigned gm = __reduce_max_sync(FULLMASK, v);
        unsigned c2 = (v == gm) ? (unsigned)ci : 0x7FFFFFFFu;
        int widx = (int)__reduce_min_sync(FULLMASK, c2);

        // centroid via broadcast L1-resident load (96KB batch fits in L1)
        cx = X[widx * 3 + 0];
        cy = X[widx * 3 + 1];
        cz = X[widx * 3 + 2];
        if (t == 0) {
            float* o = g_newxyz + (size_t)(b * SS + s + 1) * 3;
            o[0] = cx; o[1] = cy; o[2] = cz;
        }
    }
}

// =====================================================================
// K2: kNN (K=32) + group stats. Warp per query, buffered bitonic top-32.
// key = (orderable(d) << 13) | idx -> ascending u64 order == (d, idx)
// lexicographic order; selected SET == lax.top_k result. Fast path: 128
// candidates/chunk (4 per lane), ONE any-vote per chunk; keys + ballots
// only in the rare hit branch. `<=` over-admits exact boundary ties;
// merges keep the 32 smallest keys, so the final set is exact.
// =====================================================================
__device__ __forceinline__ ull u64min(ull a, ull b) { return a < b ? a : b; }
__device__ __forceinline__ ull u64max(ull a, ull b) { return a < b ? b : a; }
__device__ __forceinline__ ull makekey(float d, int idx) {
    unsigned ub = __float_as_uint(d);
    ub ^= ((unsigned)((int)ub >> 31)) | 0x80000000u;
    return ((ull)ub << 13) | (unsigned)idx;
}
__device__ __forceinline__ float kth2kd(ull kth) {  // inverse orderable
    unsigned ub = (unsigned)(kth >> 13);
    unsigned db = (ub >> 31) ? (ub ^ 0x80000000u) : ~ub;
    return __uint_as_float(db);
}
__device__ __forceinline__ ull sort32(ull key, int lane)
{
#pragma unroll
    for (int k = 2; k <= 32; k <<= 1) {
#pragma unroll
        for (int j = k >> 1; j > 0; j >>= 1) {
            ull other = __shfl_xor_sync(FULLMASK, key, j);
            bool up = ((lane & k) == 0);
            bool takeMin = (((lane & j) == 0) == up);
            key = takeMin ? u64min(key, other) : u64max(key, other);
        }
    }
    return key;
}
__device__ __forceinline__ ull merge32(ull key, ull buf, int lane)
{
    buf = sort32(buf, lane);
    ull rev = __shfl_sync(FULLMASK, buf, 31 - lane);
    key = u64min(key, rev);
#pragma unroll
    for (int j = 16; j > 0; j >>= 1) {
        ull other = __shfl_xor_sync(FULLMASK, key, j);
        bool takeMin = ((lane & j) == 0);
        key = takeMin ? u64min(key, other) : u64max(key, other);
    }
    return key;
}
// push all candidates flagged in m (uniform, nonzero) by rank; merge on fill
__device__ __forceinline__ void push_chunk(ull ck, unsigned m, int lane,
                                           ull& key, ull& kth, float& kd,
                                           ull& buf, int& bcnt)
{
    int cnt = __popc(m);
    int r = lane - bcnt;
    bool take = (r >= 0) && (r < cnt);
    unsigned pos = __fns(m, 0, take ? (r + 1) : 1);
    ull got = __shfl_sync(FULLMASK, ck, pos & 31);
    if (take) buf = got;
    bcnt += cnt;
    if (bcnt >= 32) {
        key = merge32(key, buf, lane);
        kth = __shfl_sync(FULLMASK, key, 31);
        kd = kth2kd(kth);
        int left = bcnt - 32;
        buf = ~0ull;
        if (left) {   // re-push overflow candidates (extras are harmless)
            int start = cnt - left;
            bool tk2 = lane < left;
            unsigned pos2 = __fns(m, 0, tk2 ? (start + lane + 1) : 1);
            ull got2 = __shfl_sync(FULLMASK, ck, pos2 & 31);
            if (tk2) buf = got2;
        }
        bcnt = left;
    }
}

__global__ void __launch_bounds__(1024) knn_kernel(const float* __restrict__ xyz)
{
    extern __shared__ float4 spts[];    // [NN] : x, y, z, |p|^2  (128KB)
    __shared__ double s_p1[32], s_p2[32];

    const int b  = blockIdx.x >> 3;     // 8 query-chunks (128 queries) per batch
    const int qc = blockIdx.x & 7;
    const float* X = xyz + (size_t)b * NN * 3;

    for (int p = threadIdx.x; p < NN; p += 1024) {
        float x = X[p * 3], y = X[p * 3 + 1], z = X[p * 3 + 2];
        float sq = __fadd_rn(__fadd_rn(__fmul_rn(x, x), __fmul_rn(y, y)),
                             __fmul_rn(z, z));
        spts[p] = make_float4(x, y, z, sq);
    }
    __syncthreads();

    const int warp = threadIdx.x >> 5;
    const int lane = threadIdx.x & 31;
    const ull m2two = pk2(-2.0f, -2.0f);

    double acc1 = 0.0, acc2 = 0.0;      // meaningful on lane 0 only

    for (int qi = 0; qi < 4; qi++) {
        const int s = qc * 128 + warp * 4 + qi;
        const float* cen = g_newxyz + (size_t)(b * SS + s) * 3;
        const float cx = cen[0], cy = cen[1], cz = cen[2];
        const float csq = __fadd_rn(__fadd_rn(__fmul_rn(cx, cx), __fmul_rn(cy, cy)),
                                    __fmul_rn(cz, cz));
        const ull cX2 = pk2(cx, cx), cY2 = pk2(cy, cy), cZ2 = pk2(cz, cz);
        const ull csq2 = pk2(csq, csq);

        // init list from candidates 0..63 (sort first 32, merge next 32)
        ull key;
        {
            float4 pt = spts[lane];
            float dot = __fadd_rn(__fadd_rn(__fmul_rn(pt.x, cx), __fmul_rn(pt.y, cy)),
                                  __fmul_rn(pt.z, cz));
            float d = __fadd_rn(__fadd_rn(__fmul_rn(-2.0f, dot), csq), pt.w);
            key = sort32(makekey(d, lane), lane);
            float4 p2 = spts[32 + lane];
            float dot2 = __fadd_rn(__fadd_rn(__fmul_rn(p2.x, cx), __fmul_rn(p2.y, cy)),
                                   __fmul_rn(p2.z, cz));
            float dB = __fadd_rn(__fadd_rn(__fmul_rn(-2.0f, dot2), csq), p2.w);
            key = merge32(key, makekey(dB, 32 + lane), lane);
        }
        ull kth = __shfl_sync(FULLMASK, key, 31);
        float kd = kth2kd(kth);
        ull buf = ~0ull;
        int bcnt = 0;

        // main loop: 128 candidates per chunk (4 per lane)
        int base = 64;
        for (; base + 128 <= NN; base += 128) {
            const int p0 = base + lane;
            float4 a  = spts[p0];
            float4 b4 = spts[p0 + 32];
            float4 c  = spts[p0 + 64];
            float4 e  = spts[p0 + 96];
            ull XA = pk2(a.x, b4.x), YA = pk2(a.y, b4.y);
            ull ZA = pk2(a.z, b4.z), WA = pk2(a.w, b4.w);
            ull XB = pk2(c.x, e.x),  YB = pk2(c.y, e.y);
            ull ZB = pk2(c.z, e.z),  WB = pk2(c.w, e.w);
            ull dotA = add2(add2(mul2(XA, cX2), mul2(YA, cY2)), mul2(ZA, cZ2));
            ull dotB = add2(add2(mul2(XB, cX2), mul2(YB, cY2)), mul2(ZB, cZ2));
            ull dA = add2(add2(mul2(m2two, dotA), csq2), WA);
            ull dB = add2(add2(mul2(m2two, dotB), csq2), WB);
            float d0, d1, d2, d3;
            upk2(d0, d1, dA);
            upk2(d2, d3, dB);
            bool hit = (d0 <= kd) | (d1 <= kd) | (d2 <= kd) | (d3 <= kd);
            if (__any_sync(FULLMASK, hit)) {
                unsigned m0 = __ballot_sync(FULLMASK, d0 <= kd);
                if (m0) push_chunk(makekey(d0, p0), m0, lane, key, kth, kd, buf, bcnt);
                unsigned m1 = __ballot_sync(FULLMASK, d1 <= kd);
                if (m1) push_chunk(makekey(d1, p0 + 32), m1, lane, key, kth, kd, buf, bcnt);
                unsigned m2 = __ballot_sync(FULLMASK, d2 <= kd);
                if (m2) push_chunk(makekey(d2, p0 + 64), m2, lane, key, kth, kd, buf, bcnt);
                unsigned m3 = __ballot_sync(FULLMASK, d3 <= kd);
                if (m3) push_chunk(makekey(d3, p0 + 96), m3, lane, key, kth, kd, buf, bcnt);
            }
        }
        // tail: remaining 64 candidates (2 per lane)
        for (; base < NN; base += 64) {
            const int p0 = base + lane;
            float4 a = spts[p0];
            float4 c = spts[p0 + 32];
            ull X2 = pk2(a.x, c.x), Y2 = pk2(a.y, c.y);
            ull Z2 = pk2(a.z, c.z), W2 = pk2(a.w, c.w);
            ull dot2 = add2(add2(mul2(X2, cX2), mul2(Y2, cY2)), mul2(Z2, cZ2));
            ull d2p = add2(add2(mul2(m2two, dot2), csq2), W2);
            float d0, d1;
            upk2(d0, d1, d2p);
            bool hit = (d0 <= kd) | (d1 <= kd);
            if (__any_sync(FULLMASK, hit)) {
                unsigned m0 = __ballot_sync(FULLMASK, d0 <= kd);
                if (m0) push_chunk(makekey(d0, p0), m0, lane, key, kth, kd, buf, bcnt);
                unsigned m1 = __ballot_sync(FULLMASK, d1 <= kd);
                if (m1) push_chunk(makekey(d1, p0 + 32), m1, lane, key, kth, kd, buf, bcnt);
            }
        }
        if (bcnt > 0) key = merge32(key, buf, lane);   // empty slots hold MAX

        // ----- group stats over the kept 32 neighbors -----
        int ki = (int)(key & 0x1FFFull);
        float4 q = spts[ki];
        float dx = __fsub_rn(q.x, cx);
        float dy = __fsub_rn(q.y, cy);
        float dz = __fsub_rn(q.z, cz);
        float sdx = dx, sdy = dy, sdz = dz;
        float mdx = dx, mdy = dy, mdz = dz;
        float s1 = dx + dy + dz;
        float s2 = dx * dx + dy * dy + dz * dz;
#pragma unroll
        for (int o = 16; o; o >>= 1) {
            sdx += __shfl_down_sync(FULLMASK, sdx, o);
            sdy += __shfl_down_sync(FULLMASK, sdy, o);
            sdz += __shfl_down_sync(FULLMASK, sdz, o);
            mdx = fmaxf(mdx, __shfl_down_sync(FULLMASK, mdx, o));
            mdy = fmaxf(mdy, __shfl_down_sync(FULLMASK, mdy, o));
            mdz = fmaxf(mdz, __shfl_down_sync(FULLMASK, mdz, o));
            s1 += __shfl_down_sync(FULLMASK, s1, o);
            s2 += __shfl_down_sync(FULLMASK, s2, o);
        }
        if (lane == 0) {
            int ix = (b * SS + s) * 3;
            g_gsum[ix] = sdx; g_gsum[ix + 1] = sdy; g_gsum[ix + 2] = sdz;
            g_gmax[ix] = mdx; g_gmax[ix + 1] = mdy; g_gmax[ix + 2] = mdz;
            acc1 += (double)s1;
            acc2 += (double)s2;
        }
    }

    // one atomicAdd pair per block
    if (lane == 0) { s_p1[warp] = acc1; s_p2[warp] = acc2; }
    __syncthreads();
    if (threadIdx.x == 0) {
        double a = 0.0, c = 0.0;
        for (int w = 0; w < 32; w++) { a += s_p1[w]; c += s_p2[w]; }
        atomicAdd(&g_acc[0], a);
        atomicAdd(&g_acc[1], c);
    }
}

// =====================================================================
// K3: std, lc, BN1+relu, safe_cdist, BN2+relu. Single block.
// =====================================================================
__global__ void __launch_bounds__(1024) finalize_kernel(
    const float* __restrict__ bn1g, const float* __restrict__ bn1b,
    const float* __restrict__ bn2g, const float* __restrict__ bn2b,
    float* __restrict__ out)
{
    const int t = threadIdx.x;
    const int lane = t & 31, warp = t >> 5;

    __shared__ float s_red[32];
    __shared__ float s_se;
    __shared__ float s_mean[6], s_var[6];
    __shared__ float s_tf[BB * 36];
    __shared__ float s_m2[36], s_v2[36];

    if (t == 0) {
        double M = (double)BB * SS * KK * 3;
        double var = (g_acc[1] - g_acc[0] * g_acc[0] / M) / (M - 1.0); // ddof=1
        s_se = (float)sqrt(var) + 1e-5f;
    }
    __syncthreads();
    const float se = s_se;

    for (int idx = t; idx < BB * SS; idx += 1024) {
        int b = idx >> 10, s = idx & (SS - 1);
        const float* gm = g_gmax + idx * 3;
        const float* gs = g_gsum + idx * 3;
        const float* cn = g_newxyz + idx * 3;
#pragma unroll
        for (int c = 0; c < 3; c++) {
            float mx = __fdiv_rn(gm[c], se);
            float mn = __fdiv_rn(__fdiv_rn(gs[c], 32.0f), se);
            g_lc[(b * 6 + c) * SS + s] = __fadd_rn(mx, mn);
        }
#pragma unroll
        for (int c = 0; c < 3; c++) {
            float v = cn[c];
            g_lc[(b * 6 + 3 + c) * SS + s] = v + v;
        }
    }
    __syncthreads();

    for (int c = 0; c < 6; c++) {
        float part = 0.0f;
        for (int i = t; i < BB * SS; i += 1024) {
            int b = i >> 10, s = i & 1023;
            part += g_lc[(b * 6 + c) * SS + s];
        }
#pragma unroll
        for (int o = 16; o; o >>= 1) part += __shfl_down_sync(FULLMASK, part, o);
        if (lane == 0) s_red[warp] = part;
        __syncthreads();
        if (t == 0) {
            float tot = 0.0f;
            for (int w = 0; w < 32; w++) tot += s_red[w];
            s_mean[c] = tot / (float)(BB * SS);
        }
        __syncthreads();
        float m = s_mean[c];
        part = 0.0f;
        for (int i = t; i < BB * SS; i += 1024) {
            int b = i >> 10, s = i & 1023;
            float d = g_lc[(b * 6 + c) * SS + s] - m;
            part += d * d;
        }
#pragma unroll
        for (int o = 16; o; o >>= 1) part += __shfl_down_sync(FULLMASK, part, o);
        if (lane == 0) s_red[warp] = part;
        __syncthreads();
        if (t == 0) {
            float tot = 0.0f;
            for (int w = 0; w < 32; w++) tot += s_red[w];
            s_var[c] = tot / (float)(BB * SS);   // biased, as in reference
        }
        __syncthreads();
    }
    for (int c = 0; c < 6; c++) {
        float m = s_mean[c], v = s_var[c];
        float g = bn1g[c], bt = bn1b[c];
        float den = sqrtf(v + 1e-5f);
        for (int i = t; i < BB * SS; i += 1024) {
            int b = i >> 10, s = i & 1023;
            int ix = (b * 6 + c) * SS + s;
            float y = (g_lc[ix] - m) / den * g + bt;
            g_lc[ix] = fmaxf(y, 0.0f);
        }
    }
    __syncthreads();

    if (t < BB * 6) {
        int b = t / 6, c = t % 6;
        s_tf[b * 36 + c * 6 + c] = 0.0f;
    }
    for (int task = warp; task < BB * 15; task += 32) {
        int b = task / 15, pr = task % 15;
        int i = 0, j = 0, p = pr;
        for (i = 0; i < 5; i++) {
            int row = 5 - i;
            if (p < row) { j = i + 1 + p; break; }
            p -= row;
        }
        const float* A  = g_lc + (b * 6 + i) * SS;
        const float* Bp = g_lc + (b * 6 + j) * SS;
        float part = 0.0f;
        for (int s = lane; s < SS; s += 32) {
            float d = A[s] - Bp[s];
            part += d * d;
        }
#pragma unroll
        for (int o = 16; o; o >>= 1) part += __shfl_down_sync(FULLMASK, part, o);
        if (lane == 0) {
            float v = part > 0.0f ? sqrtf(part) : 0.0f;
            s_tf[b * 36 + i * 6 + j] = v;
            s_tf[b * 36 + j * 6 + i] = v;
        }
    }
    __syncthreads();

    if (t < 36) {
        float m = 0.0f;
        for (int b = 0; b < BB; b++) m += s_tf[b * 36 + t];
        m /= (float)BB;
        float v = 0.0f;
        for (int b = 0; b < BB; b++) {
            float d = s_tf[b * 36 + t] - m;
            v += d * d;
        }
        v /= (float)BB;
        s_m2[t] = m; s_v2[t] = v;
    }
    __syncthreads();
    if (t < BB * 36) {
        int b = t / 36, f = t % 36;
        float x = s_tf[b * 36 + f];
        float y = (x - s_m2[f]) / sqrtf(s_v2[f] + 1e-5f) * bn2g[f] + bn2b[f];
        out[t] = fmaxf(y, 0.0f);
    }
}

// =====================================================================
extern "C" void kernel_launch(void* const* d_in, const int* in_sizes, int n_in,
                              void* d_out, int out_size)
{
    const float* xyz  = (const float*)d_in[0];
    const float* bn1g = (const float*)d_in[1];
    const float* bn1b = (const float*)d_in[2];
    const float* bn2g = (const float*)d_in[3];
    const float* bn2b = (const float*)d_in[4];
    float* out = (float*)d_out;

    // idempotent host-side attribute set (capture-safe)
    cudaFuncSetAttribute(knn_kernel, cudaFuncAttributeMaxDynamicSharedMemorySize,
                         NN * (int)sizeof(float4));

    fps_kernel<<<BB, 1024>>>(xyz);
    knn_kernel<<<BB * 8, 1024, NN * sizeof(float4)>>>(xyz);
    finalize_kernel<<<1, 1024>>>(bn1g, bn1b, bn2g, bn2b, out);
}